// round 8
// baseline (speedup 1.0000x reference)
#include <cuda_runtime.h>
#include <cuda_bf16.h>
#include <cstdint>

#define BB 16
#define LL 2048
#define DDIM 64
#define MT 64           // q rows per CTA
#define NTILE 64        // k cols per tile
#define NTHREADS 256
#define NIT 64          // 2 passes x 32 tiles
#define LOG2E 1.4426950408889634f

// smem: [buf:2][mat:2][n:64][128B] = 32KB, + 512B row-sum scratch
#define SM_SCR 32768u
#define SMEM_BYTES 33408

// k split-precision scratch
__device__ __nv_bfloat16 g_k_hi[BB * LL * DDIM];
__device__ __nv_bfloat16 g_k_lo[BB * LL * DDIM];

// ---------------- PTX helpers (generic-target safe) ----------------
__device__ __forceinline__ void cp16(uint32_t dst, const void* src) {
    asm volatile("cp.async.cg.shared.global [%0], [%1], 16;\n" :: "r"(dst), "l"(src));
}
__device__ __forceinline__ void cp_commit() {
    asm volatile("cp.async.commit_group;\n");
}
__device__ __forceinline__ void cp_wait0() {
    asm volatile("cp.async.wait_group 0;\n");
}
__device__ __forceinline__ float ex2(float x) {
    float r;
    asm("ex2.approx.f32 %0, %1;" : "=f"(r) : "f"(x));
    return r;
}

#define LDSM4(r0, r1, r2, r3, addr)                                        \
    asm volatile("ldmatrix.sync.aligned.m8n8.x4.shared.b16 {%0,%1,%2,%3}, [%4];" \
                 : "=r"(r0), "=r"(r1), "=r"(r2), "=r"(r3) : "r"(addr))

#define MMA_BF16(c, a, b0, b1)                                             \
    asm volatile("mma.sync.aligned.m16n8k16.row.col.f32.bf16.bf16.f32 "    \
                 "{%0,%1,%2,%3}, {%4,%5,%6,%7}, {%8,%9}, {%0,%1,%2,%3};"   \
                 : "+f"((c)[0]), "+f"((c)[1]), "+f"((c)[2]), "+f"((c)[3])  \
                 : "r"((a)[0]), "r"((a)[1]), "r"((a)[2]), "r"((a)[3]),     \
                   "r"(b0), "r"(b1))

__device__ __forceinline__ uint32_t pack2(float a, float b) {
    __nv_bfloat162 t = __floats2bfloat162_rn(a, b);
    return *reinterpret_cast<uint32_t*>(&t);
}
__device__ __forceinline__ uint32_t pack_hi(float2 f) {
    return pack2(f.x, f.y);
}
__device__ __forceinline__ uint32_t pack_lo(float2 f) {
    float hx = __bfloat162float(__float2bfloat16_rn(f.x));
    float hy = __bfloat162float(__float2bfloat16_rn(f.y));
    return pack2(f.x - hx, f.y - hy);
}

// ---------------- kernel 1: k fp32 -> bf16 hi/lo scratch ----------------
__global__ void __launch_bounds__(256)
cvt_k_kernel(const float4* __restrict__ k4) {
    int idx = blockIdx.x * 256 + threadIdx.x;
    float4 f = k4[idx];
    float hx = __bfloat162float(__float2bfloat16_rn(f.x));
    float hy = __bfloat162float(__float2bfloat16_rn(f.y));
    float hz = __bfloat162float(__float2bfloat16_rn(f.z));
    float hw = __bfloat162float(__float2bfloat16_rn(f.w));
    uint2 hi, lo;
    hi.x = pack2(f.x, f.y);            hi.y = pack2(f.z, f.w);
    lo.x = pack2(f.x - hx, f.y - hy);  lo.y = pack2(f.z - hz, f.w - hw);
    reinterpret_cast<uint2*>(g_k_hi)[idx] = hi;
    reinterpret_cast<uint2*>(g_k_lo)[idx] = lo;
}

// ---------------- k tile loader: 1024 cp16 by 256 threads ----------------
__device__ __forceinline__ void load_k_tile(uint32_t sb, int b, int tile,
                                            int buf, int tid) {
    const size_t base = ((size_t)b * LL + (size_t)tile * NTILE) * DDIM;
    #pragma unroll
    for (int rep = 0; rep < 4; rep++) {
        int cidx = tid + rep * NTHREADS;          // 0..1023
        int m = cidx >> 9;                        // 0=hi, 1=lo
        int rem = cidx & 511;
        int n = rem >> 3, ch = rem & 7;
        const __nv_bfloat16* src =
            (m ? g_k_lo : g_k_hi) + base + (size_t)n * DDIM + ch * 8;
        uint32_t dst = sb + (uint32_t)buf * 16384u + (uint32_t)m * 8192u
                     + (uint32_t)n * 128u + (uint32_t)((ch ^ (n & 7)) << 4);
        cp16(dst, src);
    }
}

// ---------------- kernel 2: attention ----------------
__global__ void __launch_bounds__(NTHREADS, 3)
attn_mma_kernel(const float* __restrict__ q, float* __restrict__ out_attn) {
    extern __shared__ char smem[];
    const uint32_t sb = (uint32_t)__cvta_generic_to_shared(smem);
    float* scr = reinterpret_cast<float*>(smem + SM_SCR);   // [2][64]
    const int tid = threadIdx.x;
    const int w = tid >> 5;
    const int l = tid & 31;
    const int wr = w & 3;         // row group: rows 16*wr
    const int wc = w >> 2;        // col half:  cols 32*wc within tile
    const int b = blockIdx.y;
    const int qt = blockIdx.x;

    // prologue: tile 0 in flight
    load_k_tile(sb, b, 0, 0, tid);
    cp_commit();

    // A fragments (q pre-scaled by log2e, split hi/lo), rows 16*wr .. +15
    uint32_t ahi[4][4], alo[4][4];
    {
        const float* q0 = q + ((size_t)b * LL + (size_t)qt * MT
                               + wr * 16 + (l >> 2)) * DDIM;
        #pragma unroll
        for (int ks = 0; ks < 4; ks++) {
            const int c0 = ks * 16 + (l & 3) * 2;
            float2 p00 = *(const float2*)(q0 + c0);
            float2 p10 = *(const float2*)(q0 + 8 * DDIM + c0);
            float2 p01 = *(const float2*)(q0 + c0 + 8);
            float2 p11 = *(const float2*)(q0 + 8 * DDIM + c0 + 8);
            p00.x *= LOG2E; p00.y *= LOG2E;
            p10.x *= LOG2E; p10.y *= LOG2E;
            p01.x *= LOG2E; p01.y *= LOG2E;
            p11.x *= LOG2E; p11.y *= LOG2E;
            ahi[ks][0] = pack_hi(p00);  alo[ks][0] = pack_lo(p00);
            ahi[ks][1] = pack_hi(p10);  alo[ks][1] = pack_lo(p10);
            ahi[ks][2] = pack_hi(p01);  alo[ks][2] = pack_lo(p01);
            ahi[ks][3] = pack_hi(p11);  alo[ks][3] = pack_lo(p11);
        }
    }

    // per-lane ldmatrix pieces
    const int rr = l & 7;
    const int mi = l >> 3;
    const int cs = mi & 1;                    // k 8-chunk select
    const int nb = ((mi >> 1) << 3) + rr;     // n offset within 16-col group

    const int r0i = 16 * wr + (l >> 2);       // CTA-local row of C[.][0,1]
    const int r1i = r0i + 8;

    float s0 = 0.f, s1 = 0.f, inv0 = 0.f, inv1 = 0.f;
    float* orow0 = out_attn + ((size_t)b * LL + (size_t)qt * MT + r0i) * (size_t)LL;
    float* orow1 = orow0 + (size_t)8 * LL;

    for (int it = 0; it < NIT; it++) {
        const int buf = it & 1;
        const int tile = it & 31;

        cp_wait0();               // tile `it` resident (own group done)
        __syncthreads();          // ...for all threads; prev compute done

        // prefetch next tile into the other buffer (safe: last read 2 iters ago)
        if (it + 1 < NIT) {
            load_k_tile(sb, b, (it + 1) & 31, buf ^ 1, tid);
            cp_commit();
        }

        // pass A -> B boundary: combine the two col-half partial sums
        if (it == 32) {
            inv0 = 1.0f / (scr[r0i] + scr[64 + r0i]);
            inv1 = 1.0f / (scr[r1i] + scr[64 + r1i]);
        }

        const uint32_t tb = sb + (uint32_t)buf * 16384u;
        float C[4][4];
        #pragma unroll
        for (int i = 0; i < 4; i++)
            C[i][0] = C[i][1] = C[i][2] = C[i][3] = 0.f;

        #pragma unroll
        for (int c = 0; c < 2; c++) {
            const uint32_t rowoff = (uint32_t)(32 * wc + 16 * c + nb) * 128u;
            #pragma unroll
            for (int ks = 0; ks < 4; ks++) {
                const uint32_t choff =
                    (uint32_t)((((ks << 1) | cs) ^ rr) << 4);
                uint32_t f0, f1, f2, f3, e0, e1, e2, e3;
                LDSM4(f0, f1, f2, f3, tb + rowoff + choff);           // hi
                LDSM4(e0, e1, e2, e3, tb + 8192u + rowoff + choff);   // lo
                MMA_BF16(C[2 * c],     ahi[ks], f0, f1);
                MMA_BF16(C[2 * c + 1], ahi[ks], f2, f3);
                MMA_BF16(C[2 * c],     alo[ks], f0, f1);
                MMA_BF16(C[2 * c + 1], alo[ks], f2, f3);
                MMA_BF16(C[2 * c],     ahi[ks], e0, e1);
                MMA_BF16(C[2 * c + 1], ahi[ks], e2, e3);
            }
        }

        if (it < 32) {
            #pragma unroll
            for (int j = 0; j < 4; j++) {
                s0 += ex2(C[j][0]) + ex2(C[j][1]);
                s1 += ex2(C[j][2]) + ex2(C[j][3]);
            }
            if (it == 31) {
                // lane-reduce over the 4 col-lanes, publish per-warp partials
                s0 += __shfl_xor_sync(0xFFFFFFFFu, s0, 1);
                s0 += __shfl_xor_sync(0xFFFFFFFFu, s0, 2);
                s1 += __shfl_xor_sync(0xFFFFFFFFu, s1, 1);
                s1 += __shfl_xor_sync(0xFFFFFFFFu, s1, 2);
                if ((l & 3) == 0) {
                    scr[wc * 64 + r0i] = s0;
                    scr[wc * 64 + r1i] = s1;
                }
            }
        } else {
            const int colb = tile * NTILE + 32 * wc + ((l & 3) << 1);
            #pragma unroll
            for (int j = 0; j < 4; j++) {
                float2 v0, v1;
                v0.x = ex2(C[j][0]) * inv0;
                v0.y = ex2(C[j][1]) * inv0;
                v1.x = ex2(C[j][2]) * inv1;
                v1.y = ex2(C[j][3]) * inv1;
                *(float2*)(orow0 + colb + j * 8) = v0;
                *(float2*)(orow1 + colb + j * 8) = v1;
            }
        }
    }
}

extern "C" void kernel_launch(void* const* d_in, const int* in_sizes, int n_in,
                              void* d_out, int out_size) {
    const float* q = (const float*)d_in[0];
    const float* k = (const float*)d_in[1];
    const float* v = (const float*)d_in[2];
    float* out = (float*)d_out;

    const size_t v_elems = (size_t)BB * LL * DDIM;
    cudaMemcpyAsync(out, v, v_elems * sizeof(float), cudaMemcpyDeviceToDevice);

    cvt_k_kernel<<<(BB * LL * DDIM / 4) / 256, 256>>>((const float4*)k);

    cudaFuncSetAttribute(attn_mma_kernel,
                         cudaFuncAttributeMaxDynamicSharedMemorySize, SMEM_BYTES);
    dim3 grid(LL / MT, BB);   // (32, 16) = 512 CTAs
    attn_mma_kernel<<<grid, NTHREADS, SMEM_BYTES>>>(q, out + v_elems);
}

// round 10
// speedup vs baseline: 1.1124x; 1.1124x over previous
#include <cuda_runtime.h>
#include <cuda_bf16.h>
#include <cstdint>

#define BB 16
#define LL 2048
#define DDIM 64
#define MT 128          // q rows per CTA
#define NTILE 128       // k cols per tile
#define NTHREADS 256
#define LOG2E 1.4426950408889634f

#define K_F4 524288     // k float4 count (16*2048*64 / 4)
#define V_F4 524288     // v float4 count (16*2048*64 / 4)

// k split-precision scratch
__device__ __nv_bfloat16 g_k_hi[BB * LL * DDIM];
__device__ __nv_bfloat16 g_k_lo[BB * LL * DDIM];

// ---------------- PTX helpers (generic-target safe) ----------------
__device__ __forceinline__ void cp16(uint32_t dst, const void* src) {
    asm volatile("cp.async.cg.shared.global [%0], [%1], 16;\n" :: "r"(dst), "l"(src));
}
__device__ __forceinline__ void cp_commit() {
    asm volatile("cp.async.commit_group;\n");
}
template <int N>
__device__ __forceinline__ void cp_wait() {
    asm volatile("cp.async.wait_group %0;\n" :: "n"(N));
}
__device__ __forceinline__ float ex2(float x) {
    float r;
    asm("ex2.approx.f32 %0, %1;" : "=f"(r) : "f"(x));
    return r;
}

#define LDSM4(r0, r1, r2, r3, addr)                                        \
    asm volatile("ldmatrix.sync.aligned.m8n8.x4.shared.b16 {%0,%1,%2,%3}, [%4];" \
                 : "=r"(r0), "=r"(r1), "=r"(r2), "=r"(r3) : "r"(addr))

#define MMA_BF16(c, a, b0, b1)                                             \
    asm volatile("mma.sync.aligned.m16n8k16.row.col.f32.bf16.bf16.f32 "    \
                 "{%0,%1,%2,%3}, {%4,%5,%6,%7}, {%8,%9}, {%0,%1,%2,%3};"   \
                 : "+f"((c)[0]), "+f"((c)[1]), "+f"((c)[2]), "+f"((c)[3])  \
                 : "r"((a)[0]), "r"((a)[1]), "r"((a)[2]), "r"((a)[3]),     \
                   "r"(b0), "r"(b1))

__device__ __forceinline__ uint32_t pack2(float a, float b) {
    __nv_bfloat162 t = __floats2bfloat162_rn(a, b);
    return *reinterpret_cast<uint32_t*>(&t);
}
__device__ __forceinline__ uint32_t pack_hi(float2 f) {
    return pack2(f.x, f.y);
}
__device__ __forceinline__ uint32_t pack_lo(float2 f) {
    float hx = __bfloat162float(__float2bfloat16_rn(f.x));
    float hy = __bfloat162float(__float2bfloat16_rn(f.y));
    return pack2(f.x - hx, f.y - hy);
}

// ------- prep: k fp32 -> bf16 hi/lo scratch, and v -> out (fused) -------
__global__ void __launch_bounds__(256)
prep_kernel(const float4* __restrict__ k4, const float4* __restrict__ v4,
            float4* __restrict__ outv4) {
    int idx = blockIdx.x * 256 + threadIdx.x;
    if (idx < K_F4) {
        float4 f = k4[idx];
        float hx = __bfloat162float(__float2bfloat16_rn(f.x));
        float hy = __bfloat162float(__float2bfloat16_rn(f.y));
        float hz = __bfloat162float(__float2bfloat16_rn(f.z));
        float hw = __bfloat162float(__float2bfloat16_rn(f.w));
        uint2 hi, lo;
        hi.x = pack2(f.x, f.y);            hi.y = pack2(f.z, f.w);
        lo.x = pack2(f.x - hx, f.y - hy);  lo.y = pack2(f.z - hz, f.w - hw);
        reinterpret_cast<uint2*>(g_k_hi)[idx] = hi;
        reinterpret_cast<uint2*>(g_k_lo)[idx] = lo;
    } else {
        int j = idx - K_F4;
        outv4[j] = v4[j];
    }
}

// ------- k tile loader: [buf:3][mat:2][n:128][128B], swizzled -------
__device__ __forceinline__ void load_k_tile(uint32_t sb, int b, int tile,
                                            int buf, int tid) {
    const size_t base = ((size_t)b * LL + (size_t)tile * NTILE) * DDIM;
    #pragma unroll
    for (int rep = 0; rep < 8; rep++) {
        const int m = rep >> 2;                      // 0=hi, 1=lo
        int cidx = tid + (rep & 3) * NTHREADS;       // 0..1023 per matrix
        int n = cidx >> 3, ch = cidx & 7;
        const __nv_bfloat16* src =
            (m ? g_k_lo : g_k_hi) + base + (size_t)n * DDIM + ch * 8;
        uint32_t dst = sb + (uint32_t)buf * 32768u + (uint32_t)m * 16384u
                     + (uint32_t)n * 128u + (uint32_t)((ch ^ (n & 7)) << 4);
        cp16(dst, src);
    }
}

// ------- core MMA for one 64-col half of the current tile -------
struct Frag { uint32_t ahi[4][4]; uint32_t alo[4][4]; };

__device__ __forceinline__ void compute_half(
    float C[8][4], uint32_t bhiB, uint32_t bloB, int half,
    const Frag& fr, int rr, int cs, int nb)
{
    #pragma unroll
    for (int i = 0; i < 8; i++)
        C[i][0] = C[i][1] = C[i][2] = C[i][3] = 0.f;

    #pragma unroll
    for (int ks = 0; ks < 4; ks++) {
        const uint32_t choff = (uint32_t)((((ks << 1) | cs) ^ rr) << 4);
        uint32_t f0[4], f1[4], f2[4], f3[4];

        #pragma unroll
        for (int j = 0; j < 4; j++) {
            const uint32_t rowoff = (uint32_t)(half * 64 + j * 16 + nb) * 128u;
            LDSM4(f0[j], f1[j], f2[j], f3[j], bhiB + rowoff + choff);
        }
        #pragma unroll
        for (int j = 0; j < 4; j++)
            MMA_BF16(C[2 * j], fr.ahi[ks], f0[j], f1[j]);
        #pragma unroll
        for (int j = 0; j < 4; j++)
            MMA_BF16(C[2 * j + 1], fr.ahi[ks], f2[j], f3[j]);
        #pragma unroll
        for (int j = 0; j < 4; j++)
            MMA_BF16(C[2 * j], fr.alo[ks], f0[j], f1[j]);
        #pragma unroll
        for (int j = 0; j < 4; j++)
            MMA_BF16(C[2 * j + 1], fr.alo[ks], f2[j], f3[j]);

        #pragma unroll
        for (int j = 0; j < 4; j++) {
            const uint32_t rowoff = (uint32_t)(half * 64 + j * 16 + nb) * 128u;
            LDSM4(f0[j], f1[j], f2[j], f3[j], bloB + rowoff + choff);
        }
        #pragma unroll
        for (int j = 0; j < 4; j++)
            MMA_BF16(C[2 * j], fr.ahi[ks], f0[j], f1[j]);
        #pragma unroll
        for (int j = 0; j < 4; j++)
            MMA_BF16(C[2 * j + 1], fr.ahi[ks], f2[j], f3[j]);
    }
}

// ---------------- attention kernel ----------------
__global__ void __launch_bounds__(NTHREADS, 2)
attn_mma_kernel(const float* __restrict__ q, float* __restrict__ out_attn) {
    extern __shared__ char smem[];
    const uint32_t sb = (uint32_t)__cvta_generic_to_shared(smem);
    const int tid = threadIdx.x;
    const int w = tid >> 5;
    const int l = tid & 31;
    const int b = blockIdx.y;
    const int qt = blockIdx.x;

    // prologue: tiles 0,1 in flight
    load_k_tile(sb, b, 0, 0, tid);
    cp_commit();
    load_k_tile(sb, b, 1, 1, tid);
    cp_commit();

    // A fragments (q pre-scaled by log2e, split hi/lo)
    Frag fr;
    {
        const float* q0 = q + ((size_t)b * LL + (size_t)qt * MT
                               + w * 16 + (l >> 2)) * DDIM;
        #pragma unroll
        for (int ks = 0; ks < 4; ks++) {
            const int c0 = ks * 16 + (l & 3) * 2;
            float2 p00 = *(const float2*)(q0 + c0);
            float2 p10 = *(const float2*)(q0 + 8 * DDIM + c0);
            float2 p01 = *(const float2*)(q0 + c0 + 8);
            float2 p11 = *(const float2*)(q0 + 8 * DDIM + c0 + 8);
            p00.x *= LOG2E; p00.y *= LOG2E;
            p10.x *= LOG2E; p10.y *= LOG2E;
            p01.x *= LOG2E; p01.y *= LOG2E;
            p11.x *= LOG2E; p11.y *= LOG2E;
            fr.ahi[ks][0] = pack_hi(p00);  fr.alo[ks][0] = pack_lo(p00);
            fr.ahi[ks][1] = pack_hi(p10);  fr.alo[ks][1] = pack_lo(p10);
            fr.ahi[ks][2] = pack_hi(p01);  fr.alo[ks][2] = pack_lo(p01);
            fr.ahi[ks][3] = pack_hi(p11);  fr.alo[ks][3] = pack_lo(p11);
        }
    }

    // per-lane ldmatrix pieces
    const int rr = l & 7;
    const int mi = l >> 3;
    const int cs = mi & 1;
    const int nb = ((mi >> 1) << 3) + rr;

    float s00 = 0.f, s01 = 0.f, s10 = 0.f, s11 = 0.f;
    float* orow0 = out_attn + ((size_t)b * LL + (size_t)qt * MT
                               + w * 16 + (l >> 2)) * (size_t)LL;
    float* orow1 = orow0 + (size_t)8 * LL;

    // =================== pass A: row sums of exp ===================
    for (int it = 0; it < 16; it++) {
        const int buf = it % 3;
        cp_wait<1>();
        __syncthreads();

        load_k_tile(sb, b, (it + 2) & 15, (it + 2) % 3, tid);
        cp_commit();

        const uint32_t bhiB = sb + (uint32_t)buf * 32768u;
        const uint32_t bloB = bhiB + 16384u;

        #pragma unroll
        for (int half = 0; half < 2; half++) {
            float C[8][4];
            compute_half(C, bhiB, bloB, half, fr, rr, cs, nb);
            #pragma unroll
            for (int nf = 0; nf < 8; nf++) {
                s00 += ex2(C[nf][0]);
                s01 += ex2(C[nf][1]);
                s10 += ex2(C[nf][2]);
                s11 += ex2(C[nf][3]);
            }
        }
    }

    // finalize row sums -> inverses
    float inv0, inv1;
    {
        float sum0 = s00 + s01;
        float sum1 = s10 + s11;
        sum0 += __shfl_xor_sync(0xFFFFFFFFu, sum0, 1);
        sum0 += __shfl_xor_sync(0xFFFFFFFFu, sum0, 2);
        sum1 += __shfl_xor_sync(0xFFFFFFFFu, sum1, 1);
        sum1 += __shfl_xor_sync(0xFFFFFFFFu, sum1, 2);
        inv0 = 1.0f / sum0;
        inv1 = 1.0f / sum1;
    }

    // =================== pass B: recompute, normalize, store ===================
    for (int it = 16; it < 32; it++) {
        const int buf = it % 3;
        const int tile = it & 15;
        cp_wait<1>();
        __syncthreads();

        if (it + 2 < 32) {
            load_k_tile(sb, b, (it + 2) & 15, (it + 2) % 3, tid);
            cp_commit();
        } else {
            cp_commit();   // keep one group per iter so wait<1> stays exact
        }

        const uint32_t bhiB = sb + (uint32_t)buf * 32768u;
        const uint32_t bloB = bhiB + 16384u;

        #pragma unroll
        for (int half = 0; half < 2; half++) {
            float C[8][4];
            compute_half(C, bhiB, bloB, half, fr, rr, cs, nb);
            const int colb = tile * NTILE + half * 64 + ((l & 3) << 1);
            #pragma unroll
            for (int nf = 0; nf < 8; nf++) {
                float2 v0, v1;
                v0.x = ex2(C[nf][0]) * inv0;
                v0.y = ex2(C[nf][1]) * inv0;
                v1.x = ex2(C[nf][2]) * inv1;
                v1.y = ex2(C[nf][3]) * inv1;
                *(float2*)(orow0 + colb + nf * 8) = v0;
                *(float2*)(orow1 + colb + nf * 8) = v1;
            }
        }
    }
}

extern "C" void kernel_launch(void* const* d_in, const int* in_sizes, int n_in,
                              void* d_out, int out_size) {
    const float* q = (const float*)d_in[0];
    const float* k = (const float*)d_in[1];
    const float* v = (const float*)d_in[2];
    float* out = (float*)d_out;

    const size_t v_elems = (size_t)BB * LL * DDIM;

    prep_kernel<<<(K_F4 + V_F4) / 256, 256>>>((const float4*)k,
                                              (const float4*)v,
                                              (float4*)out);

    cudaFuncSetAttribute(attn_mma_kernel,
                         cudaFuncAttributeMaxDynamicSharedMemorySize, 98304);
    dim3 grid(LL / MT, BB);   // (16, 16) = 256 CTAs
    attn_mma_kernel<<<grid, NTHREADS, 98304>>>(q, out + v_elems);
}

// round 11
// speedup vs baseline: 1.1678x; 1.0499x over previous
#include <cuda_runtime.h>
#include <cuda_bf16.h>
#include <cstdint>

#define BB 16
#define LL 2048
#define DDIM 64
#define MT 128          // q rows per CTA
#define NTILE 64        // k cols per tile
#define NTILES 32
#define NTHREADS 128    // 4 warps, each 32 rows x 64 cols
#define LOG2E 1.4426950408889634f

#define K_F4 524288
#define V_F4 524288

#define TILE_BYTES 16384u   // [mat:2][n:64][128B]
#define SMEM_BYTES (3 * 16384)

__device__ __nv_bfloat16 g_k_hi[BB * LL * DDIM];
__device__ __nv_bfloat16 g_k_lo[BB * LL * DDIM];

// ---------------- PTX helpers (generic-target safe) ----------------
__device__ __forceinline__ void cp16(uint32_t dst, const void* src) {
    asm volatile("cp.async.cg.shared.global [%0], [%1], 16;\n" :: "r"(dst), "l"(src));
}
__device__ __forceinline__ void cp_commit() {
    asm volatile("cp.async.commit_group;\n");
}
template <int N>
__device__ __forceinline__ void cp_wait() {
    asm volatile("cp.async.wait_group %0;\n" :: "n"(N));
}
__device__ __forceinline__ float ex2(float x) {
    float r;
    asm("ex2.approx.f32 %0, %1;" : "=f"(r) : "f"(x));
    return r;
}

#define LDSM4(r0, r1, r2, r3, addr)                                        \
    asm volatile("ldmatrix.sync.aligned.m8n8.x4.shared.b16 {%0,%1,%2,%3}, [%4];" \
                 : "=r"(r0), "=r"(r1), "=r"(r2), "=r"(r3) : "r"(addr))

#define MMA_BF16(c, a, b0, b1)                                             \
    asm volatile("mma.sync.aligned.m16n8k16.row.col.f32.bf16.bf16.f32 "    \
                 "{%0,%1,%2,%3}, {%4,%5,%6,%7}, {%8,%9}, {%0,%1,%2,%3};"   \
                 : "+f"((c)[0]), "+f"((c)[1]), "+f"((c)[2]), "+f"((c)[3])  \
                 : "r"((a)[0]), "r"((a)[1]), "r"((a)[2]), "r"((a)[3]),     \
                   "r"(b0), "r"(b1))

__device__ __forceinline__ uint32_t pack2(float a, float b) {
    __nv_bfloat162 t = __floats2bfloat162_rn(a, b);
    return *reinterpret_cast<uint32_t*>(&t);
}
__device__ __forceinline__ uint32_t pack_hi(float2 f) {
    return pack2(f.x, f.y);
}
__device__ __forceinline__ uint32_t pack_lo(float2 f) {
    float hx = __bfloat162float(__float2bfloat16_rn(f.x));
    float hy = __bfloat162float(__float2bfloat16_rn(f.y));
    return pack2(f.x - hx, f.y - hy);
}

// ------- prep: k -> bf16 hi/lo scratch; v -> out (fused) -------
__global__ void __launch_bounds__(256)
prep_kernel(const float4* __restrict__ k4, const float4* __restrict__ v4,
            float4* __restrict__ outv4) {
    int idx = blockIdx.x * 256 + threadIdx.x;
    if (idx < K_F4) {
        float4 f = k4[idx];
        float hx = __bfloat162float(__float2bfloat16_rn(f.x));
        float hy = __bfloat162float(__float2bfloat16_rn(f.y));
        float hz = __bfloat162float(__float2bfloat16_rn(f.z));
        float hw = __bfloat162float(__float2bfloat16_rn(f.w));
        uint2 hi, lo;
        hi.x = pack2(f.x, f.y);            hi.y = pack2(f.z, f.w);
        lo.x = pack2(f.x - hx, f.y - hy);  lo.y = pack2(f.z - hz, f.w - hw);
        reinterpret_cast<uint2*>(g_k_hi)[idx] = hi;
        reinterpret_cast<uint2*>(g_k_lo)[idx] = lo;
    } else {
        int j = idx - K_F4;
        outv4[j] = v4[j];
    }
}

// ------- k tile loader: 1024 cp16 by 128 threads -------
__device__ __forceinline__ void load_k_tile(uint32_t sb, int b, int tile,
                                            int buf, int tid) {
    const size_t base = ((size_t)b * LL + (size_t)tile * NTILE) * DDIM;
    #pragma unroll
    for (int rep = 0; rep < 8; rep++) {
        int cidx = tid + rep * NTHREADS;   // 0..1023
        int m = cidx >> 9;                 // 0=hi, 1=lo
        int rem = cidx & 511;
        int n = rem >> 3, ch = rem & 7;
        const __nv_bfloat16* src =
            (m ? g_k_lo : g_k_hi) + base + (size_t)n * DDIM + ch * 8;
        uint32_t dst = sb + (uint32_t)buf * TILE_BYTES + (uint32_t)m * 8192u
                     + (uint32_t)n * 128u + (uint32_t)((ch ^ (n & 7)) << 4);
        cp16(dst, src);
    }
}

struct Frag { uint32_t ahi[2][4][4]; uint32_t alo[2][4][4]; };

// ------- core: one 64-col tile, 32 rows (2 m-blocks), 192 MMAs -------
__device__ __forceinline__ void compute_tile(
    float C[2][8][4], uint32_t tb, const Frag& fr, int rr, int cs, int nb)
{
    #pragma unroll
    for (int mb = 0; mb < 2; mb++)
        #pragma unroll
        for (int i = 0; i < 8; i++)
            C[mb][i][0] = C[mb][i][1] = C[mb][i][2] = C[mb][i][3] = 0.f;

    #pragma unroll
    for (int ks = 0; ks < 4; ks++) {
        const uint32_t choff = (uint32_t)((((ks << 1) | cs) ^ rr) << 4);
        uint32_t f0[4], f1[4], f2[4], f3[4];

        // hi B fragments (feed ahi AND alo for both m-blocks: 32 MMAs)
        #pragma unroll
        for (int j = 0; j < 4; j++) {
            const uint32_t rowoff = (uint32_t)(j * 16 + nb) * 128u;
            LDSM4(f0[j], f1[j], f2[j], f3[j], tb + rowoff + choff);
        }
        #pragma unroll
        for (int j = 0; j < 4; j++) MMA_BF16(C[0][2*j],   fr.ahi[0][ks], f0[j], f1[j]);
        #pragma unroll
        for (int j = 0; j < 4; j++) MMA_BF16(C[0][2*j+1], fr.ahi[0][ks], f2[j], f3[j]);
        #pragma unroll
        for (int j = 0; j < 4; j++) MMA_BF16(C[1][2*j],   fr.ahi[1][ks], f0[j], f1[j]);
        #pragma unroll
        for (int j = 0; j < 4; j++) MMA_BF16(C[1][2*j+1], fr.ahi[1][ks], f2[j], f3[j]);
        #pragma unroll
        for (int j = 0; j < 4; j++) MMA_BF16(C[0][2*j],   fr.alo[0][ks], f0[j], f1[j]);
        #pragma unroll
        for (int j = 0; j < 4; j++) MMA_BF16(C[0][2*j+1], fr.alo[0][ks], f2[j], f3[j]);
        #pragma unroll
        for (int j = 0; j < 4; j++) MMA_BF16(C[1][2*j],   fr.alo[1][ks], f0[j], f1[j]);
        #pragma unroll
        for (int j = 0; j < 4; j++) MMA_BF16(C[1][2*j+1], fr.alo[1][ks], f2[j], f3[j]);

        // lo B fragments (feed ahi for both m-blocks: 16 MMAs)
        #pragma unroll
        for (int j = 0; j < 4; j++) {
            const uint32_t rowoff = (uint32_t)(j * 16 + nb) * 128u;
            LDSM4(f0[j], f1[j], f2[j], f3[j], tb + 8192u + rowoff + choff);
        }
        #pragma unroll
        for (int j = 0; j < 4; j++) MMA_BF16(C[0][2*j],   fr.ahi[0][ks], f0[j], f1[j]);
        #pragma unroll
        for (int j = 0; j < 4; j++) MMA_BF16(C[0][2*j+1], fr.ahi[0][ks], f2[j], f3[j]);
        #pragma unroll
        for (int j = 0; j < 4; j++) MMA_BF16(C[1][2*j],   fr.ahi[1][ks], f0[j], f1[j]);
        #pragma unroll
        for (int j = 0; j < 4; j++) MMA_BF16(C[1][2*j+1], fr.ahi[1][ks], f2[j], f3[j]);
    }
}

// ---------------- attention kernel ----------------
__global__ void __launch_bounds__(NTHREADS, 2)
attn_mma_kernel(const float* __restrict__ q, float* __restrict__ out_attn) {
    extern __shared__ char smem[];
    const uint32_t sb = (uint32_t)__cvta_generic_to_shared(smem);
    const int tid = threadIdx.x;
    const int w = tid >> 5;
    const int l = tid & 31;
    const int b = blockIdx.y;
    const int qt = blockIdx.x;

    // prologue: tiles 0,1 in flight
    load_k_tile(sb, b, 0, 0, tid);
    cp_commit();
    load_k_tile(sb, b, 1, 1, tid);
    cp_commit();

    // A fragments: warp w owns rows 32w..32w+31 (two m16 blocks)
    Frag fr;
    #pragma unroll
    for (int mb = 0; mb < 2; mb++) {
        const float* q0 = q + ((size_t)b * LL + (size_t)qt * MT
                               + w * 32 + mb * 16 + (l >> 2)) * DDIM;
        #pragma unroll
        for (int ks = 0; ks < 4; ks++) {
            const int c0 = ks * 16 + (l & 3) * 2;
            float2 p00 = *(const float2*)(q0 + c0);
            float2 p10 = *(const float2*)(q0 + 8 * DDIM + c0);
            float2 p01 = *(const float2*)(q0 + c0 + 8);
            float2 p11 = *(const float2*)(q0 + 8 * DDIM + c0 + 8);
            p00.x *= LOG2E; p00.y *= LOG2E;
            p10.x *= LOG2E; p10.y *= LOG2E;
            p01.x *= LOG2E; p01.y *= LOG2E;
            p11.x *= LOG2E; p11.y *= LOG2E;
            fr.ahi[mb][ks][0] = pack_hi(p00);  fr.alo[mb][ks][0] = pack_lo(p00);
            fr.ahi[mb][ks][1] = pack_hi(p10);  fr.alo[mb][ks][1] = pack_lo(p10);
            fr.ahi[mb][ks][2] = pack_hi(p01);  fr.alo[mb][ks][2] = pack_lo(p01);
            fr.ahi[mb][ks][3] = pack_hi(p11);  fr.alo[mb][ks][3] = pack_lo(p11);
        }
    }

    const int rr = l & 7;
    const int mi = l >> 3;
    const int cs = mi & 1;
    const int nb = ((mi >> 1) << 3) + rr;

    float s0 = 0.f, s1 = 0.f, s2 = 0.f, s3 = 0.f;

    // row pointers: r0 = 32w + (l>>2); rows r0, r0+8, r0+16, r0+24
    float* orow0 = out_attn + ((size_t)b * LL + (size_t)qt * MT
                               + w * 32 + (l >> 2)) * (size_t)LL;
    float* orow1 = orow0 + (size_t)8 * LL;
    float* orow2 = orow0 + (size_t)16 * LL;
    float* orow3 = orow0 + (size_t)24 * LL;

    // =================== pass A: row sums of exp2 ===================
    for (int it = 0; it < NTILES; it++) {
        const int buf = it % 3;
        cp_wait<1>();
        __syncthreads();

        load_k_tile(sb, b, (it + 2) & 31, (it + 2) % 3, tid);
        cp_commit();

        float C[2][8][4];
        compute_tile(C, sb + (uint32_t)buf * TILE_BYTES, fr, rr, cs, nb);

        #pragma unroll
        for (int nf = 0; nf < 8; nf++) {
            s0 += ex2(C[0][nf][0]) + ex2(C[0][nf][1]);
            s1 += ex2(C[0][nf][2]) + ex2(C[0][nf][3]);
            s2 += ex2(C[1][nf][0]) + ex2(C[1][nf][1]);
            s3 += ex2(C[1][nf][2]) + ex2(C[1][nf][3]);
        }
    }

    float inv0, inv1, inv2, inv3;
    {
        s0 += __shfl_xor_sync(0xFFFFFFFFu, s0, 1);
        s0 += __shfl_xor_sync(0xFFFFFFFFu, s0, 2);
        s1 += __shfl_xor_sync(0xFFFFFFFFu, s1, 1);
        s1 += __shfl_xor_sync(0xFFFFFFFFu, s1, 2);
        s2 += __shfl_xor_sync(0xFFFFFFFFu, s2, 1);
        s2 += __shfl_xor_sync(0xFFFFFFFFu, s2, 2);
        s3 += __shfl_xor_sync(0xFFFFFFFFu, s3, 1);
        s3 += __shfl_xor_sync(0xFFFFFFFFu, s3, 2);
        inv0 = 1.0f / s0;
        inv1 = 1.0f / s1;
        inv2 = 1.0f / s2;
        inv3 = 1.0f / s3;
    }

    // =================== pass B: recompute, normalize, store ===================
    for (int g = NTILES; g < 2 * NTILES; g++) {
        const int buf = g % 3;
        const int tile = g & 31;
        cp_wait<1>();
        __syncthreads();

        if (g + 2 < 2 * NTILES) {
            load_k_tile(sb, b, (g + 2) & 31, (g + 2) % 3, tid);
            cp_commit();
        } else {
            cp_commit();
        }

        float C[2][8][4];
        compute_tile(C, sb + (uint32_t)buf * TILE_BYTES, fr, rr, cs, nb);

        const int colb = tile * NTILE + ((l & 3) << 1);
        #pragma unroll
        for (int nf = 0; nf < 8; nf++) {
            const int co = colb + nf * 8;
            float2 v;
            v.x = ex2(C[0][nf][0]) * inv0;
            v.y = ex2(C[0][nf][1]) * inv0;
            *(float2*)(orow0 + co) = v;
            v.x = ex2(C[0][nf][2]) * inv1;
            v.y = ex2(C[0][nf][3]) * inv1;
            *(float2*)(orow1 + co) = v;
            v.x = ex2(C[1][nf][0]) * inv2;
            v.y = ex2(C[1][nf][1]) * inv2;
            *(float2*)(orow2 + co) = v;
            v.x = ex2(C[1][nf][2]) * inv3;
            v.y = ex2(C[1][nf][3]) * inv3;
            *(float2*)(orow3 + co) = v;
        }
    }
}

extern "C" void kernel_launch(void* const* d_in, const int* in_sizes, int n_in,
                              void* d_out, int out_size) {
    const float* q = (const float*)d_in[0];
    const float* k = (const float*)d_in[1];
    const float* v = (const float*)d_in[2];
    float* out = (float*)d_out;

    const size_t v_elems = (size_t)BB * LL * DDIM;

    prep_kernel<<<(K_F4 + V_F4) / 256, 256>>>((const float4*)k,
                                              (const float4*)v,
                                              (float4*)out);

    cudaFuncSetAttribute(attn_mma_kernel,
                         cudaFuncAttributeMaxDynamicSharedMemorySize, SMEM_BYTES);
    dim3 grid(LL / MT, BB);   // (16, 16) = 256 CTAs
    attn_mma_kernel<<<grid, NTHREADS, SMEM_BYTES>>>(q, out + v_elems);
}

// round 12
// speedup vs baseline: 1.1808x; 1.0111x over previous
#include <cuda_runtime.h>
#include <cuda_bf16.h>
#include <cstdint>

#define BB 16
#define LL 2048
#define DDIM 64
#define MT 128          // q rows per CTA
#define NTILE 64        // k cols per tile
#define NTILES 32
#define NTHREADS 128    // 4 warps, each 32 rows x 64 cols
#define LOG2E 1.4426950408889634f

#define K_F4 524288
#define V_F4 524288

#define TILE_BYTES 16384u   // [mat:2][n:64][128B]
#define SMEM_BYTES (3 * 16384)

__device__ __nv_bfloat16 g_k_hi[BB * LL * DDIM];
__device__ __nv_bfloat16 g_k_lo[BB * LL * DDIM];

// ---------------- PTX helpers (generic-target safe) ----------------
__device__ __forceinline__ void cp16(uint32_t dst, const void* src) {
    asm volatile("cp.async.cg.shared.global [%0], [%1], 16;\n" :: "r"(dst), "l"(src));
}
__device__ __forceinline__ void cp_commit() {
    asm volatile("cp.async.commit_group;\n");
}
template <int N>
__device__ __forceinline__ void cp_wait() {
    asm volatile("cp.async.wait_group %0;\n" :: "n"(N));
}
__device__ __forceinline__ float ex2(float x) {
    float r;
    asm("ex2.approx.f32 %0, %1;" : "=f"(r) : "f"(x));
    return r;
}

#define LDSM4(r0, r1, r2, r3, addr)                                        \
    asm volatile("ldmatrix.sync.aligned.m8n8.x4.shared.b16 {%0,%1,%2,%3}, [%4];" \
                 : "=r"(r0), "=r"(r1), "=r"(r2), "=r"(r3) : "r"(addr))

#define MMA_BF16(c, a, b0, b1)                                             \
    asm volatile("mma.sync.aligned.m16n8k16.row.col.f32.bf16.bf16.f32 "    \
                 "{%0,%1,%2,%3}, {%4,%5,%6,%7}, {%8,%9}, {%0,%1,%2,%3};"   \
                 : "+f"((c)[0]), "+f"((c)[1]), "+f"((c)[2]), "+f"((c)[3])  \
                 : "r"((a)[0]), "r"((a)[1]), "r"((a)[2]), "r"((a)[3]),     \
                   "r"(b0), "r"(b1))

__device__ __forceinline__ uint32_t pack2(float a, float b) {
    __nv_bfloat162 t = __floats2bfloat162_rn(a, b);
    return *reinterpret_cast<uint32_t*>(&t);
}
__device__ __forceinline__ uint32_t pack_hi(float2 f) {
    return pack2(f.x, f.y);
}
__device__ __forceinline__ uint32_t pack_lo(float2 f) {
    float hx = __bfloat162float(__float2bfloat16_rn(f.x));
    float hy = __bfloat162float(__float2bfloat16_rn(f.y));
    return pack2(f.x - hx, f.y - hy);
}

// ------- prep: k -> bf16 hi/lo scratch; v -> out (fused) -------
__global__ void __launch_bounds__(256)
prep_kernel(const float4* __restrict__ k4, const float4* __restrict__ v4,
            float4* __restrict__ outv4) {
    int idx = blockIdx.x * 256 + threadIdx.x;
    if (idx < K_F4) {
        float4 f = k4[idx];
        float hx = __bfloat162float(__float2bfloat16_rn(f.x));
        float hy = __bfloat162float(__float2bfloat16_rn(f.y));
        float hz = __bfloat162float(__float2bfloat16_rn(f.z));
        float hw = __bfloat162float(__float2bfloat16_rn(f.w));
        uint2 hi, lo;
        hi.x = pack2(f.x, f.y);            hi.y = pack2(f.z, f.w);
        lo.x = pack2(f.x - hx, f.y - hy);  lo.y = pack2(f.z - hz, f.w - hw);
        reinterpret_cast<uint2*>(g_k_hi)[idx] = hi;
        reinterpret_cast<uint2*>(g_k_lo)[idx] = lo;
    } else {
        int j = idx - K_F4;
        outv4[j] = v4[j];
    }
}

// ------- k tile loader: 1024 cp16 by 128 threads -------
__device__ __forceinline__ void load_k_tile(uint32_t sb, int b, int tile,
                                            int buf, int tid) {
    const size_t base = ((size_t)b * LL + (size_t)tile * NTILE) * DDIM;
    #pragma unroll
    for (int rep = 0; rep < 8; rep++) {
        int cidx = tid + rep * NTHREADS;   // 0..1023
        int m = cidx >> 9;                 // 0=hi, 1=lo
        int rem = cidx & 511;
        int n = rem >> 3, ch = rem & 7;
        const __nv_bfloat16* src =
            (m ? g_k_lo : g_k_hi) + base + (size_t)n * DDIM + ch * 8;
        uint32_t dst = sb + (uint32_t)buf * TILE_BYTES + (uint32_t)m * 8192u
                     + (uint32_t)n * 128u + (uint32_t)((ch ^ (n & 7)) << 4);
        cp16(dst, src);
    }
}

struct Frag { uint32_t ahi[2][4][4]; uint32_t alo[2][4][4]; };

// ------- core: one 64-col tile, 32 rows, LDSM pipelined (depth 1) -------
// 8 batches: even = hi frags(ks=bt/2) -> 32 MMAs; odd = lo frags -> 16 MMAs.
__device__ __forceinline__ void compute_tile(
    float C[2][8][4], uint32_t tb, const Frag& fr, int rr, int cs, int nb)
{
    #pragma unroll
    for (int mb = 0; mb < 2; mb++)
        #pragma unroll
        for (int i = 0; i < 8; i++)
            C[mb][i][0] = C[mb][i][1] = C[mb][i][2] = C[mb][i][3] = 0.f;

    uint32_t rowoffs[4], choffs[4];
    #pragma unroll
    for (int j = 0; j < 4; j++)
        rowoffs[j] = (uint32_t)(j * 16 + nb) * 128u;
    #pragma unroll
    for (int ks = 0; ks < 4; ks++)
        choffs[ks] = (uint32_t)((((ks << 1) | cs) ^ rr) << 4);

    uint32_t f[2][16];

    // prime: batch 0 (hi, ks=0)
    {
        const uint32_t base = tb + choffs[0];
        #pragma unroll
        for (int j = 0; j < 4; j++)
            LDSM4(f[0][4*j], f[0][4*j+1], f[0][4*j+2], f[0][4*j+3],
                  base + rowoffs[j]);
    }

    #pragma unroll
    for (int bt = 0; bt < 8; bt++) {
        const int ks  = bt >> 1;
        const int cur = bt & 1;
        const int nxt = cur ^ 1;

        // prefetch next batch while this batch's MMAs issue
        if (bt < 7) {
            const int nbt = bt + 1;
            const uint32_t base = tb + ((nbt & 1) ? 8192u : 0u)
                                + choffs[nbt >> 1];
            #pragma unroll
            for (int j = 0; j < 4; j++)
                LDSM4(f[nxt][4*j], f[nxt][4*j+1], f[nxt][4*j+2], f[nxt][4*j+3],
                      base + rowoffs[j]);
        }

        if (!(bt & 1)) {
            // hi batch: ahi & alo, both m-blocks -> 32 MMAs
            #pragma unroll
            for (int j = 0; j < 4; j++) MMA_BF16(C[0][2*j],   fr.ahi[0][ks], f[cur][4*j],   f[cur][4*j+1]);
            #pragma unroll
            for (int j = 0; j < 4; j++) MMA_BF16(C[0][2*j+1], fr.ahi[0][ks], f[cur][4*j+2], f[cur][4*j+3]);
            #pragma unroll
            for (int j = 0; j < 4; j++) MMA_BF16(C[1][2*j],   fr.ahi[1][ks], f[cur][4*j],   f[cur][4*j+1]);
            #pragma unroll
            for (int j = 0; j < 4; j++) MMA_BF16(C[1][2*j+1], fr.ahi[1][ks], f[cur][4*j+2], f[cur][4*j+3]);
            #pragma unroll
            for (int j = 0; j < 4; j++) MMA_BF16(C[0][2*j],   fr.alo[0][ks], f[cur][4*j],   f[cur][4*j+1]);
            #pragma unroll
            for (int j = 0; j < 4; j++) MMA_BF16(C[0][2*j+1], fr.alo[0][ks], f[cur][4*j+2], f[cur][4*j+3]);
            #pragma unroll
            for (int j = 0; j < 4; j++) MMA_BF16(C[1][2*j],   fr.alo[1][ks], f[cur][4*j],   f[cur][4*j+1]);
            #pragma unroll
            for (int j = 0; j < 4; j++) MMA_BF16(C[1][2*j+1], fr.alo[1][ks], f[cur][4*j+2], f[cur][4*j+3]);
        } else {
            // lo batch: ahi only, both m-blocks -> 16 MMAs
            #pragma unroll
            for (int j = 0; j < 4; j++) MMA_BF16(C[0][2*j],   fr.ahi[0][ks], f[cur][4*j],   f[cur][4*j+1]);
            #pragma unroll
            for (int j = 0; j < 4; j++) MMA_BF16(C[0][2*j+1], fr.ahi[0][ks], f[cur][4*j+2], f[cur][4*j+3]);
            #pragma unroll
            for (int j = 0; j < 4; j++) MMA_BF16(C[1][2*j],   fr.ahi[1][ks], f[cur][4*j],   f[cur][4*j+1]);
            #pragma unroll
            for (int j = 0; j < 4; j++) MMA_BF16(C[1][2*j+1], fr.ahi[1][ks], f[cur][4*j+2], f[cur][4*j+3]);
        }
    }
}

// ---------------- attention kernel ----------------
__global__ void __launch_bounds__(NTHREADS, 2)
attn_mma_kernel(const float* __restrict__ q, float* __restrict__ out_attn) {
    extern __shared__ char smem[];
    const uint32_t sb = (uint32_t)__cvta_generic_to_shared(smem);
    const int tid = threadIdx.x;
    const int w = tid >> 5;
    const int l = tid & 31;
    const int b = blockIdx.y;
    const int qt = blockIdx.x;

    // prologue: tiles 0,1 in flight
    load_k_tile(sb, b, 0, 0, tid);
    cp_commit();
    load_k_tile(sb, b, 1, 1, tid);
    cp_commit();

    // A fragments: warp w owns rows 32w..32w+31 (two m16 blocks)
    Frag fr;
    #pragma unroll
    for (int mb = 0; mb < 2; mb++) {
        const float* q0 = q + ((size_t)b * LL + (size_t)qt * MT
                               + w * 32 + mb * 16 + (l >> 2)) * DDIM;
        #pragma unroll
        for (int ks = 0; ks < 4; ks++) {
            const int c0 = ks * 16 + (l & 3) * 2;
            float2 p00 = *(const float2*)(q0 + c0);
            float2 p10 = *(const float2*)(q0 + 8 * DDIM + c0);
            float2 p01 = *(const float2*)(q0 + c0 + 8);
            float2 p11 = *(const float2*)(q0 + 8 * DDIM + c0 + 8);
            p00.x *= LOG2E; p00.y *= LOG2E;
            p10.x *= LOG2E; p10.y *= LOG2E;
            p01.x *= LOG2E; p01.y *= LOG2E;
            p11.x *= LOG2E; p11.y *= LOG2E;
            fr.ahi[mb][ks][0] = pack_hi(p00);  fr.alo[mb][ks][0] = pack_lo(p00);
            fr.ahi[mb][ks][1] = pack_hi(p10);  fr.alo[mb][ks][1] = pack_lo(p10);
            fr.ahi[mb][ks][2] = pack_hi(p01);  fr.alo[mb][ks][2] = pack_lo(p01);
            fr.ahi[mb][ks][3] = pack_hi(p11);  fr.alo[mb][ks][3] = pack_lo(p11);
        }
    }

    const int rr = l & 7;
    const int mi = l >> 3;
    const int cs = mi & 1;
    const int nb = ((mi >> 1) << 3) + rr;

    float s0 = 0.f, s1 = 0.f, s2 = 0.f, s3 = 0.f;

    float* orow0 = out_attn + ((size_t)b * LL + (size_t)qt * MT
                               + w * 32 + (l >> 2)) * (size_t)LL;
    float* orow1 = orow0 + (size_t)8 * LL;
    float* orow2 = orow0 + (size_t)16 * LL;
    float* orow3 = orow0 + (size_t)24 * LL;

    // =================== pass A: row sums of exp2 ===================
    for (int it = 0; it < NTILES; it++) {
        const int buf = it % 3;
        cp_wait<1>();
        __syncthreads();

        load_k_tile(sb, b, (it + 2) & 31, (it + 2) % 3, tid);
        cp_commit();

        float C[2][8][4];
        compute_tile(C, sb + (uint32_t)buf * TILE_BYTES, fr, rr, cs, nb);

        #pragma unroll
        for (int nf = 0; nf < 8; nf++) {
            s0 += ex2(C[0][nf][0]) + ex2(C[0][nf][1]);
            s1 += ex2(C[0][nf][2]) + ex2(C[0][nf][3]);
            s2 += ex2(C[1][nf][0]) + ex2(C[1][nf][1]);
            s3 += ex2(C[1][nf][2]) + ex2(C[1][nf][3]);
        }
    }

    float inv0, inv1, inv2, inv3;
    {
        s0 += __shfl_xor_sync(0xFFFFFFFFu, s0, 1);
        s0 += __shfl_xor_sync(0xFFFFFFFFu, s0, 2);
        s1 += __shfl_xor_sync(0xFFFFFFFFu, s1, 1);
        s1 += __shfl_xor_sync(0xFFFFFFFFu, s1, 2);
        s2 += __shfl_xor_sync(0xFFFFFFFFu, s2, 1);
        s2 += __shfl_xor_sync(0xFFFFFFFFu, s2, 2);
        s3 += __shfl_xor_sync(0xFFFFFFFFu, s3, 1);
        s3 += __shfl_xor_sync(0xFFFFFFFFu, s3, 2);
        inv0 = 1.0f / s0;
        inv1 = 1.0f / s1;
        inv2 = 1.0f / s2;
        inv3 = 1.0f / s3;
    }

    // =================== pass B: recompute, normalize, store ===================
    for (int g = NTILES; g < 2 * NTILES; g++) {
        const int buf = g % 3;
        const int tile = g & 31;
        cp_wait<1>();
        __syncthreads();

        if (g + 2 < 2 * NTILES) {
            load_k_tile(sb, b, (g + 2) & 31, (g + 2) % 3, tid);
            cp_commit();
        } else {
            cp_commit();
        }

        float C[2][8][4];
        compute_tile(C, sb + (uint32_t)buf * TILE_BYTES, fr, rr, cs, nb);

        const int colb = tile * NTILE + ((l & 3) << 1);
        #pragma unroll
        for (int nf = 0; nf < 8; nf++) {
            const int co = colb + nf * 8;
            float2 v;
            v.x = ex2(C[0][nf][0]) * inv0;
            v.y = ex2(C[0][nf][1]) * inv0;
            *(float2*)(orow0 + co) = v;
            v.x = ex2(C[0][nf][2]) * inv1;
            v.y = ex2(C[0][nf][3]) * inv1;
            *(float2*)(orow1 + co) = v;
            v.x = ex2(C[1][nf][0]) * inv2;
            v.y = ex2(C[1][nf][1]) * inv2;
            *(float2*)(orow2 + co) = v;
            v.x = ex2(C[1][nf][2]) * inv3;
            v.y = ex2(C[1][nf][3]) * inv3;
            *(float2*)(orow3 + co) = v;
        }
    }
}

extern "C" void kernel_launch(void* const* d_in, const int* in_sizes, int n_in,
                              void* d_out, int out_size) {
    const float* q = (const float*)d_in[0];
    const float* k = (const float*)d_in[1];
    const float* v = (const float*)d_in[2];
    float* out = (float*)d_out;

    const size_t v_elems = (size_t)BB * LL * DDIM;

    prep_kernel<<<(K_F4 + V_F4) / 256, 256>>>((const float4*)k,
                                              (const float4*)v,
                                              (float4*)out);

    cudaFuncSetAttribute(attn_mma_kernel,
                         cudaFuncAttributeMaxDynamicSharedMemorySize, SMEM_BYTES);
    dim3 grid(LL / MT, BB);   // (16, 16) = 256 CTAs
    attn_mma_kernel<<<grid, NTHREADS, SMEM_BYTES>>>(q, out + v_elems);
}